// round 12
// baseline (speedup 1.0000x reference)
#include <cuda_runtime.h>
#include <cuda_bf16.h>
#include <cuda_fp16.h>
#include <cstdint>

#define NN 50000
#define EE 800000
#define INDIM 256
#define HH 128
#define LLAYERS 4
#define CC 10
#define LN_EPS 1e-5f

// ---------------- scratch (device globals; no allocation) ----------------
__device__ int   d_indeg[2][NN];
__device__ int   d_rowptr[2][NN + 1];
__device__ int   d_cursor[2][NN];
__device__ float d_dinv[2][NN];
__device__ __align__(16) int2 d_edge[2][EE];      // {src, w_bits}
__device__ float d_x[2][(size_t)NN * HH];
__device__ __align__(16) __half d_h[2][(size_t)NN * HH];
__device__ int   d_blksum[2][64];

// pre-transposed, bf16-split weights: layout [n][k] (K-major rows of W^T)
__device__ __align__(16) __nv_bfloat16 d_wredT_h[2][HH * INDIM];
__device__ __align__(16) __nv_bfloat16 d_wredT_l[2][HH * INDIM];
__device__ __align__(16) __nv_bfloat16 d_wT_h[2][LLAYERS][HH * HH];
__device__ __align__(16) __nv_bfloat16 d_wT_l[2][LLAYERS][HH * HH];

// ---------------- PTX helpers ----------------
__device__ __forceinline__ uint32_t smem_u32(const void* p) {
    uint32_t a;
    asm("{ .reg .u64 t; cvta.to.shared.u64 t, %1; cvt.u32.u64 %0, t; }" : "=r"(a) : "l"(p));
    return a;
}

__device__ __forceinline__ void ldsm4(uint32_t* r, uint32_t addr) {
    asm volatile("ldmatrix.sync.aligned.m8n8.x4.shared.b16 {%0,%1,%2,%3}, [%4];"
                 : "=r"(r[0]), "=r"(r[1]), "=r"(r[2]), "=r"(r[3]) : "r"(addr));
}

__device__ __forceinline__ void mma16816(float* d, const uint32_t* a, const uint32_t* b) {
    asm volatile(
        "mma.sync.aligned.m16n8k16.row.col.f32.bf16.bf16.f32 "
        "{%0,%1,%2,%3}, {%4,%5,%6,%7}, {%8,%9}, {%0,%1,%2,%3};"
        : "+f"(d[0]), "+f"(d[1]), "+f"(d[2]), "+f"(d[3])
        : "r"(a[0]), "r"(a[1]), "r"(a[2]), "r"(a[3]), "r"(b[0]), "r"(b[1]));
}

#define CP_ASYNC16(dst, src) \
    asm volatile("cp.async.cg.shared.global [%0], [%1], 16;" :: "r"(dst), "l"(src))
#define CP_COMMIT() asm volatile("cp.async.commit_group;")
#define CP_WAIT0()  asm volatile("cp.async.wait_group 0;" ::: "memory")

// ---------------- CSR build (gridDim.y = 2 : both graph-streams per launch) ----
__global__ void k_zero() {
    int s = blockIdx.y;
    int i = blockIdx.x * blockDim.x + threadIdx.x;
    if (i < NN) d_indeg[s][i] = 0;
}

__global__ void k_hist(const int* __restrict__ dst0, const int* __restrict__ dst1) {
    int s = blockIdx.y;
    const int* dst = s ? dst1 : dst0;
    int e = blockIdx.x * blockDim.x + threadIdx.x;
    if (e < EE) atomicAdd(&d_indeg[s][dst[e]], 1);
}

__global__ void k_scan1() {
    __shared__ int sh[1024];
    int s = blockIdx.y;
    int b = blockIdx.x, t = threadIdx.x, i = b * 1024 + t;
    int v = (i < NN) ? d_indeg[s][i] : 0;
    sh[t] = v;
    __syncthreads();
    #pragma unroll
    for (int off = 1; off < 1024; off <<= 1) {
        int x = (t >= off) ? sh[t - off] : 0;
        __syncthreads();
        sh[t] += x;
        __syncthreads();
    }
    if (i < NN) {
        d_rowptr[s][i] = sh[t] - v;
        d_dinv[s][i]   = rsqrtf((float)(v + 1));
    }
    if (t == 1023) d_blksum[s][b] = sh[t];
}

__global__ void k_scan2() {
    __shared__ int sh[64];
    int s = blockIdx.y;
    int t = threadIdx.x;
    int v = (t < 49) ? d_blksum[s][t] : 0;
    sh[t] = v;
    __syncthreads();
    #pragma unroll
    for (int off = 1; off < 64; off <<= 1) {
        int x = (t >= off) ? sh[t - off] : 0;
        __syncthreads();
        sh[t] += x;
        __syncthreads();
    }
    if (t < 49) d_blksum[s][t] = sh[t] - v;
}

__global__ void k_scan3() {
    int s = blockIdx.y;
    int b = blockIdx.x, i = b * 1024 + threadIdx.x;
    if (i < NN) {
        int r = d_rowptr[s][i] + d_blksum[s][b];
        d_rowptr[s][i] = r;
        d_cursor[s][i] = r;
    }
    if (i == 0) d_rowptr[s][NN] = EE;
}

// fill packed edge records: {src, dinv[src]}
__global__ void k_fill(const int* __restrict__ src0, const int* __restrict__ dst0,
                       const int* __restrict__ src1, const int* __restrict__ dst1) {
    int s = blockIdx.y;
    const int* src = s ? src1 : src0;
    const int* dst = s ? dst1 : dst0;
    int e = blockIdx.x * blockDim.x + threadIdx.x;
    if (e < EE) {
        int u = src[e];
        int pos = atomicAdd(&d_cursor[s][dst[e]], 1);
        d_edge[s][pos] = make_int2(u, __float_as_int(d_dinv[s][u]));
    }
}

// ---------------- weight prep: transpose + bf16 hi/lo split ----------------
__global__ void k_prep(const float* __restrict__ Wred0, const float* __restrict__ Wred1,
                       const float* __restrict__ W0, const float* __restrict__ W1) {
    const int PER_STREAM = INDIM * HH + LLAYERS * HH * HH;
    int i = blockIdx.x * blockDim.x + threadIdx.x;
    if (i >= 2 * PER_STREAM) return;
    int s = i >= PER_STREAM;
    int j = i - s * PER_STREAM;
    float w;
    __nv_bfloat16 *ph, *pl;
    if (j < INDIM * HH) {
        int k = j >> 7, n = j & 127;
        w = (s ? Wred1 : Wred0)[k * HH + n];
        ph = &d_wredT_h[s][n * INDIM + k];
        pl = &d_wredT_l[s][n * INDIM + k];
    } else {
        int r = j - INDIM * HH;
        int l = r >> 14;
        int k = (r >> 7) & 127, n = r & 127;
        w = (s ? W1 : W0)[l * HH * HH + k * HH + n];
        ph = &d_wT_h[s][l][n * HH + k];
        pl = &d_wT_l[s][l][n * HH + k];
    }
    __nv_bfloat16 h = __float2bfloat16(w);
    *ph = h;
    *pl = __float2bfloat16(w - __bfloat162float(h));
}

// ---------------- mma.sync bf16 GEMM (3-pass compensated), batched over s ----
template <int KTOT, bool HOUT>
__global__ void __launch_bounds__(256) k_gemm_mma(
    const float* __restrict__ A0, const float* __restrict__ A1,
    const float* __restrict__ bias0, const float* __restrict__ bias1,
    int l, int M)
{
    constexpr int RS = 80;
    __shared__ __align__(16) char smem[4 * 128 * RS];
    const uint32_t AS_H = smem_u32(smem);
    const uint32_t AS_L = AS_H + 128 * RS;
    const uint32_t BS_H = AS_H + 2 * 128 * RS;
    const uint32_t BS_L = AS_H + 3 * 128 * RS;

    int s = blockIdx.y;
    const float* A = s ? A1 : A0;
    const float* bias = s ? bias1 : bias0;
    const __nv_bfloat16* Bh = (KTOT == INDIM) ? d_wredT_h[s] : d_wT_h[s][l];
    const __nv_bfloat16* Bl = (KTOT == INDIM) ? d_wredT_l[s] : d_wT_l[s][l];

    int tid = threadIdx.x, w = tid >> 5, lane = tid & 31;
    int row0 = blockIdx.x * 128;
    int wm = (w >> 1) * 32, wn = (w & 1) * 64;

    float acc[2][8][4];
    #pragma unroll
    for (int i = 0; i < 2; i++)
        #pragma unroll
        for (int j = 0; j < 8; j++)
            #pragma unroll
            for (int q = 0; q < 4; q++) acc[i][j][q] = 0.f;

    int lrow = tid >> 1, lhalf = tid & 1;
    bool avalid = (row0 + lrow) < M;
    const float* aptr = A + (size_t)(row0 + lrow) * KTOT + lhalf * 16;
    const __nv_bfloat16* bhp = Bh + (size_t)lrow * KTOT + lhalf * 16;
    const __nv_bfloat16* blp = Bl + (size_t)lrow * KTOT + lhalf * 16;
    uint32_t ash_st = AS_H + lrow * RS + lhalf * 32;
    uint32_t asl_st = AS_L + lrow * RS + lhalf * 32;
    uint32_t bsh_st = BS_H + lrow * RS + lhalf * 32;
    uint32_t bsl_st = BS_L + lrow * RS + lhalf * 32;

    int a_r = lane & 15, a_k = (lane >> 4) * 8;
    int b_r = ((lane >> 4) << 3) + (lane & 7), b_k = ((lane >> 3) & 1) * 8;

    for (int c0 = 0; c0 < KTOT; c0 += 32) {
        CP_ASYNC16(bsh_st,      bhp);
        CP_ASYNC16(bsh_st + 16, bhp + 8);
        CP_ASYNC16(bsl_st,      blp);
        CP_ASYNC16(bsl_st + 16, blp + 8);
        CP_COMMIT();
        bhp += 32; blp += 32;

        float xv[16];
        if (avalid) {
            #pragma unroll
            for (int g = 0; g < 4; g++) {
                float4 v = *(const float4*)(aptr + g * 4);
                xv[g * 4] = v.x; xv[g * 4 + 1] = v.y; xv[g * 4 + 2] = v.z; xv[g * 4 + 3] = v.w;
            }
        } else {
            #pragma unroll
            for (int j = 0; j < 16; j++) xv[j] = 0.f;
        }
        aptr += 32;
        union { uint4 q[2]; __nv_bfloat16 b[16]; } hi, lo;
        #pragma unroll
        for (int j = 0; j < 16; j++) {
            __nv_bfloat16 h = __float2bfloat16(xv[j]);
            hi.b[j] = h;
            lo.b[j] = __float2bfloat16(xv[j] - __bfloat162float(h));
        }
        asm volatile("st.shared.v4.b32 [%0], {%1,%2,%3,%4};" :: "r"(ash_st),
            "r"(hi.q[0].x), "r"(hi.q[0].y), "r"(hi.q[0].z), "r"(hi.q[0].w));
        asm volatile("st.shared.v4.b32 [%0], {%1,%2,%3,%4};" :: "r"(ash_st + 16),
            "r"(hi.q[1].x), "r"(hi.q[1].y), "r"(hi.q[1].z), "r"(hi.q[1].w));
        asm volatile("st.shared.v4.b32 [%0], {%1,%2,%3,%4};" :: "r"(asl_st),
            "r"(lo.q[0].x), "r"(lo.q[0].y), "r"(lo.q[0].z), "r"(lo.q[0].w));
        asm volatile("st.shared.v4.b32 [%0], {%1,%2,%3,%4};" :: "r"(asl_st + 16),
            "r"(lo.q[1].x), "r"(lo.q[1].y), "r"(lo.q[1].z), "r"(lo.q[1].w));

        CP_WAIT0();
        __syncthreads();

        #pragma unroll
        for (int ks = 0; ks < 2; ks++) {
            int kb = ks * 16;
            uint32_t ah[2][4], al[2][4];
            #pragma unroll
            for (int mt = 0; mt < 2; mt++) {
                uint32_t off = (uint32_t)((wm + mt * 16 + a_r) * RS + (kb + a_k) * 2);
                ldsm4(ah[mt], AS_H + off);
                ldsm4(al[mt], AS_L + off);
            }
            uint32_t bh[4][4], bl[4][4];
            #pragma unroll
            for (int nt = 0; nt < 4; nt++) {
                uint32_t off = (uint32_t)((wn + nt * 16 + b_r) * RS + (kb + b_k) * 2);
                ldsm4(bh[nt], BS_H + off);
                ldsm4(bl[nt], BS_L + off);
            }
            #pragma unroll
            for (int mt = 0; mt < 2; mt++) {
                #pragma unroll
                for (int j = 0; j < 8; j++) {
                    const uint32_t* ph = &bh[j >> 1][(j & 1) * 2];
                    const uint32_t* pl = &bl[j >> 1][(j & 1) * 2];
                    mma16816(acc[mt][j], ah[mt], ph);
                    mma16816(acc[mt][j], ah[mt], pl);
                    mma16816(acc[mt][j], al[mt], ph);
                }
            }
        }
        __syncthreads();
    }

    int qr = lane >> 2, qc = (lane & 3) * 2;
    #pragma unroll
    for (int mt = 0; mt < 2; mt++) {
        int r0g = row0 + wm + mt * 16 + qr;
        #pragma unroll
        for (int j = 0; j < 8; j++) {
            int col = wn + j * 8 + qc;
            float b0 = 0.f, b1 = 0.f;
            if (bias) { b0 = bias[col]; b1 = bias[col + 1]; }
            if (HOUT) {
                __half* Ch = d_h[s];
                if (r0g < M)
                    *(__half2*)(Ch + (size_t)r0g * HH + col) =
                        __floats2half2_rn(acc[mt][j][0] + b0, acc[mt][j][1] + b1);
                if (r0g + 8 < M)
                    *(__half2*)(Ch + (size_t)(r0g + 8) * HH + col) =
                        __floats2half2_rn(acc[mt][j][2] + b0, acc[mt][j][3] + b1);
            } else {
                float* Cf = d_x[s];
                if (r0g < M)
                    *(float2*)(Cf + (size_t)r0g * HH + col) =
                        make_float2(acc[mt][j][0] + b0, acc[mt][j][1] + b1);
                if (r0g + 8 < M)
                    *(float2*)(Cf + (size_t)(r0g + 8) * HH + col) =
                        make_float2(acc[mt][j][2] + b0, acc[mt][j][3] + b1);
            }
        }
    }
}

// ---------------- fused GCN aggregate + bias + LayerNorm + ReLU + residual ----------------
// warp per node; h fp16; R8 coalesced layout (lane -> channels {2L,2L+1,64+2L,64+2L+1});
// FOUR independent edge chains per iteration for MLP.
__global__ void __launch_bounds__(256) k_agg(
    const float* __restrict__ b0p, const float* __restrict__ b1p,
    const float* __restrict__ g0p, const float* __restrict__ g1p,
    const float* __restrict__ e0p, const float* __restrict__ e1p,
    int l)
{
    int s = blockIdx.y;
    int v = (blockIdx.x * blockDim.x + threadIdx.x) >> 5;
    int lane = threadIdx.x & 31;
    if (v >= NN) return;

    const float* bias  = (s ? b1p : b0p) + l * HH;
    const float* gamma = (s ? g1p : g0p) + l * HH;
    const float* beta  = (s ? e1p : e0p) + l * HH;
    const __half2* h2 = (const __half2*)d_h[s];   // row stride 64 half2
    const int2* edges = d_edge[s];
    float* x = d_x[s];

    // 4 chains x 4 channels
    float A0[4] = {0.f, 0.f, 0.f, 0.f};
    float A1[4] = {0.f, 0.f, 0.f, 0.f};
    float A2[4] = {0.f, 0.f, 0.f, 0.f};
    float A3[4] = {0.f, 0.f, 0.f, 0.f};

    int beg = d_rowptr[s][v], end = d_rowptr[s][v + 1];
    float dv = d_dinv[s][v];

    int i = beg;
    for (; i + 4 <= end; i += 4) {
        int2 e0 = edges[i];
        int2 e1 = edges[i + 1];
        int2 e2 = edges[i + 2];
        int2 e3 = edges[i + 3];
        float w0 = __int_as_float(e0.y), w1 = __int_as_float(e1.y);
        float w2 = __int_as_float(e2.y), w3 = __int_as_float(e3.y);
        const __half2* p0 = h2 + (size_t)e0.x * 64;
        const __half2* p1 = h2 + (size_t)e1.x * 64;
        const __half2* p2 = h2 + (size_t)e2.x * 64;
        const __half2* p3 = h2 + (size_t)e3.x * 64;
        float2 q0a = __half22float2(p0[lane]), q0b = __half22float2(p0[lane + 32]);
        float2 q1a = __half22float2(p1[lane]), q1b = __half22float2(p1[lane + 32]);
        float2 q2a = __half22float2(p2[lane]), q2b = __half22float2(p2[lane + 32]);
        float2 q3a = __half22float2(p3[lane]), q3b = __half22float2(p3[lane + 32]);
        A0[0] += w0 * q0a.x; A0[1] += w0 * q0a.y; A0[2] += w0 * q0b.x; A0[3] += w0 * q0b.y;
        A1[0] += w1 * q1a.x; A1[1] += w1 * q1a.y; A1[2] += w1 * q1b.x; A1[3] += w1 * q1b.y;
        A2[0] += w2 * q2a.x; A2[1] += w2 * q2a.y; A2[2] += w2 * q2b.x; A2[3] += w2 * q2b.y;
        A3[0] += w3 * q3a.x; A3[1] += w3 * q3a.y; A3[2] += w3 * q3b.x; A3[3] += w3 * q3b.y;
    }
    if (i + 2 <= end) {
        int2 e0 = edges[i];
        int2 e1 = edges[i + 1];
        float w0 = __int_as_float(e0.y), w1 = __int_as_float(e1.y);
        const __half2* p0 = h2 + (size_t)e0.x * 64;
        const __half2* p1 = h2 + (size_t)e1.x * 64;
        float2 q0a = __half22float2(p0[lane]), q0b = __half22float2(p0[lane + 32]);
        float2 q1a = __half22float2(p1[lane]), q1b = __half22float2(p1[lane + 32]);
        A0[0] += w0 * q0a.x; A0[1] += w0 * q0a.y; A0[2] += w0 * q0b.x; A0[3] += w0 * q0b.y;
        A1[0] += w1 * q1a.x; A1[1] += w1 * q1a.y; A1[2] += w1 * q1b.x; A1[3] += w1 * q1b.y;
        i += 2;
    }
    if (i < end) {
        int2 e0 = edges[i];
        float w0 = __int_as_float(e0.y);
        const __half2* p0 = h2 + (size_t)e0.x * 64;
        float2 qa = __half22float2(p0[lane]), qb = __half22float2(p0[lane + 32]);
        A2[0] += w0 * qa.x; A2[1] += w0 * qa.y; A2[2] += w0 * qb.x; A2[3] += w0 * qb.y;
    }
    // self loop -> chain 3
    {
        const __half2* p = h2 + (size_t)v * 64;
        float2 qa = __half22float2(p[lane]), qb = __half22float2(p[lane + 32]);
        A3[0] += dv * qa.x; A3[1] += dv * qa.y; A3[2] += dv * qb.x; A3[3] += dv * qb.y;
    }

    float a0 = A0[0] + A1[0] + A2[0] + A3[0];
    float a1 = A0[1] + A1[1] + A2[1] + A3[1];
    float a2 = A0[2] + A1[2] + A2[2] + A3[2];
    float a3 = A0[3] + A1[3] + A2[3] + A3[3];

    int ch0 = 2 * lane, ch2 = 64 + 2 * lane;
    a0 = a0 * dv + bias[ch0];
    a1 = a1 * dv + bias[ch0 + 1];
    a2 = a2 * dv + bias[ch2];
    a3 = a3 * dv + bias[ch2 + 1];

    float sum = a0 + a1 + a2 + a3;
    #pragma unroll
    for (int o = 16; o; o >>= 1) sum += __shfl_xor_sync(0xFFFFFFFFu, sum, o);
    float mu = sum * (1.f / HH);
    float v0 = a0 - mu, v1 = a1 - mu, v2 = a2 - mu, v3 = a3 - mu;
    float var = v0 * v0 + v1 * v1 + v2 * v2 + v3 * v3;
    #pragma unroll
    for (int o = 16; o; o >>= 1) var += __shfl_xor_sync(0xFFFFFFFFu, var, o);
    var *= (1.f / HH);
    float rstd = rsqrtf(var + LN_EPS);

    float2* xp = (float2*)(x + (size_t)v * HH);
    float2 r0 = xp[lane], r1 = xp[lane + 32];
    r0.x += fmaxf(v0 * rstd * gamma[ch0]     + beta[ch0],     0.f);
    r0.y += fmaxf(v1 * rstd * gamma[ch0 + 1] + beta[ch0 + 1], 0.f);
    r1.x += fmaxf(v2 * rstd * gamma[ch2]     + beta[ch2],     0.f);
    r1.y += fmaxf(v3 * rstd * gamma[ch2 + 1] + beta[ch2 + 1], 0.f);
    xp[lane] = r0;
    xp[lane + 32] = r1;
}

// ---------------- classifier ----------------
__global__ void __launch_bounds__(256) k_cls(const float* __restrict__ Wcls,
                                             const float* __restrict__ bcls,
                                             float* __restrict__ out) {
    __shared__ float WsT[CC * 2 * HH];
    __shared__ float bs[CC];
    for (int i = threadIdx.x; i < 2 * HH * CC; i += blockDim.x) {
        int k = i / CC, c = i % CC;
        WsT[c * (2 * HH) + k] = Wcls[i];
    }
    if (threadIdx.x < CC) bs[threadIdx.x] = bcls[threadIdx.x];
    __syncthreads();

    int v = (blockIdx.x * blockDim.x + threadIdx.x) >> 5;
    int lane = threadIdx.x & 31;
    if (v >= NN) return;

    float acc[CC];
    #pragma unroll
    for (int c = 0; c < CC; c++) acc[c] = 0.f;

    const float* a = d_x[0] + (size_t)v * HH;
    const float* b = d_x[1] + (size_t)v * HH;
    #pragma unroll
    for (int kk = 0; kk < 4; kk++) {
        int k = lane + 32 * kk;
        float av = a[k];
        float bv = b[k];
        #pragma unroll
        for (int c = 0; c < CC; c++) {
            acc[c] += av * WsT[c * (2 * HH) + k];
            acc[c] += bv * WsT[c * (2 * HH) + 128 + k];
        }
    }
    #pragma unroll
    for (int c = 0; c < CC; c++)
        #pragma unroll
        for (int o = 16; o; o >>= 1) acc[c] += __shfl_xor_sync(0xFFFFFFFFu, acc[c], o);

    if (lane == 0) {
        float* op = out + (size_t)v * CC;
        #pragma unroll
        for (int c = 0; c < CC; c++) op[c] = acc[c] + bs[c];
    }
}

// ---------------- driver (single default stream — graph-capture safe) ----------------
extern "C" void kernel_launch(void* const* d_in, const int* in_sizes, int n_in,
                              void* d_out, int out_size) {
    const float* x_in[2]  = { (const float*)d_in[0], (const float*)d_in[1] };
    const float* Wred[2]  = { (const float*)d_in[2], (const float*)d_in[4] };
    const float* bred[2]  = { (const float*)d_in[3], (const float*)d_in[5] };
    const float* W[2]     = { (const float*)d_in[6],  (const float*)d_in[10] };
    const float* b[2]     = { (const float*)d_in[7],  (const float*)d_in[11] };
    const float* g[2]     = { (const float*)d_in[8],  (const float*)d_in[12] };
    const float* be[2]    = { (const float*)d_in[9],  (const float*)d_in[13] };
    const float* Wcls     = (const float*)d_in[14];
    const float* bcls     = (const float*)d_in[15];
    const int*   ei[2]    = { (const int*)d_in[16], (const int*)d_in[17] };
    float* out = (float*)d_out;

    void* p0;
    cudaGetSymbolAddress(&p0, d_x);
    float* px = (float*)p0;

    const int THR = 256;
    const dim3 gN((NN + THR - 1) / THR, 2);
    const dim3 gE((EE + THR - 1) / THR, 2);
    const dim3 gW((NN * 32 + THR - 1) / THR, 2);
    const dim3 gG((NN + 127) / 128, 2);
    const dim3 gS((NN + 1023) / 1024, 2);
    const dim3 gS2(1, 2);
    const int blkWarp1 = (NN * 32 + THR - 1) / THR;

    {
        const int TOT = 2 * (INDIM * HH + LLAYERS * HH * HH);
        k_prep<<<(TOT + THR - 1) / THR, THR>>>(Wred[0], Wred[1], W[0], W[1]);
    }

    // CSR build (both streams per launch)
    k_zero<<<gN, THR>>>();
    k_hist<<<gE, THR>>>(ei[0] + EE, ei[1] + EE);
    k_scan1<<<gS, 1024>>>();
    k_scan2<<<gS2, 64>>>();
    k_scan3<<<gS, 1024>>>();
    k_fill<<<gE, THR>>>(ei[0], ei[0] + EE, ei[1], ei[1] + EE);

    // dim-reduction GEMM (both streams)
    k_gemm_mma<INDIM, false><<<gG, 256>>>(x_in[0], x_in[1], bred[0], bred[1], 0, NN);

    // 4 layers (both streams per launch)
    for (int l = 0; l < LLAYERS; l++) {
        k_gemm_mma<HH, true><<<gG, 256>>>(px, px + (size_t)NN * HH, nullptr, nullptr, l, NN);
        k_agg<<<gW, THR>>>(b[0], b[1], g[0], g[1], be[0], be[1], l);
    }

    k_cls<<<blkWarp1, THR>>>(Wcls, bcls, out);
}

// round 15
// speedup vs baseline: 1.0946x; 1.0946x over previous
#include <cuda_runtime.h>
#include <cuda_bf16.h>
#include <cuda_fp16.h>
#include <cstdint>

#define NN 50000
#define EE 800000
#define INDIM 256
#define HH 128
#define LLAYERS 4
#define CC 10
#define LN_EPS 1e-5f

// ---------------- scratch (device globals; no allocation) ----------------
__device__ int   d_indeg[2][NN];
__device__ int   d_rowptr[2][NN + 1];
__device__ int   d_cursor[2][NN];
__device__ float d_dinv[2][NN];
__device__ __align__(16) int2 d_edge[2][EE];      // {src, w_bits}
__device__ float d_x[2][(size_t)NN * HH];
__device__ __align__(16) __half d_h[2][(size_t)NN * HH];
__device__ int   d_blksum[2][64];

// pre-transposed, bf16-split weights: layout [n][k] (K-major rows of W^T)
__device__ __align__(16) __nv_bfloat16 d_wredT_h[2][HH * INDIM];
__device__ __align__(16) __nv_bfloat16 d_wredT_l[2][HH * INDIM];
__device__ __align__(16) __nv_bfloat16 d_wT_h[2][LLAYERS][HH * HH];
__device__ __align__(16) __nv_bfloat16 d_wT_l[2][LLAYERS][HH * HH];

// ---------------- PTX helpers ----------------
__device__ __forceinline__ uint32_t smem_u32(const void* p) {
    uint32_t a;
    asm("{ .reg .u64 t; cvta.to.shared.u64 t, %1; cvt.u32.u64 %0, t; }" : "=r"(a) : "l"(p));
    return a;
}

__device__ __forceinline__ void ldsm4(uint32_t* r, uint32_t addr) {
    asm volatile("ldmatrix.sync.aligned.m8n8.x4.shared.b16 {%0,%1,%2,%3}, [%4];"
                 : "=r"(r[0]), "=r"(r[1]), "=r"(r[2]), "=r"(r[3]) : "r"(addr));
}

__device__ __forceinline__ void mma16816(float* d, const uint32_t* a, const uint32_t* b) {
    asm volatile(
        "mma.sync.aligned.m16n8k16.row.col.f32.bf16.bf16.f32 "
        "{%0,%1,%2,%3}, {%4,%5,%6,%7}, {%8,%9}, {%0,%1,%2,%3};"
        : "+f"(d[0]), "+f"(d[1]), "+f"(d[2]), "+f"(d[3])
        : "r"(a[0]), "r"(a[1]), "r"(a[2]), "r"(a[3]), "r"(b[0]), "r"(b[1]));
}

#define STS128(addr, q) \
    asm volatile("st.shared.v4.b32 [%0], {%1,%2,%3,%4};" :: "r"(addr), \
        "r"((q).x), "r"((q).y), "r"((q).z), "r"((q).w))

// ---------------- CSR build (gridDim.y = 2 : both graph-streams per launch) ----
__global__ void k_zero() {
    int s = blockIdx.y;
    int i = blockIdx.x * blockDim.x + threadIdx.x;
    if (i < NN) d_indeg[s][i] = 0;
}

__global__ void k_hist(const int* __restrict__ dst0, const int* __restrict__ dst1) {
    int s = blockIdx.y;
    const int* dst = s ? dst1 : dst0;
    int e = blockIdx.x * blockDim.x + threadIdx.x;
    if (e < EE) atomicAdd(&d_indeg[s][dst[e]], 1);
}

__global__ void k_scan1() {
    __shared__ int sh[1024];
    int s = blockIdx.y;
    int b = blockIdx.x, t = threadIdx.x, i = b * 1024 + t;
    int v = (i < NN) ? d_indeg[s][i] : 0;
    sh[t] = v;
    __syncthreads();
    #pragma unroll
    for (int off = 1; off < 1024; off <<= 1) {
        int x = (t >= off) ? sh[t - off] : 0;
        __syncthreads();
        sh[t] += x;
        __syncthreads();
    }
    if (i < NN) {
        d_rowptr[s][i] = sh[t] - v;
        d_dinv[s][i]   = rsqrtf((float)(v + 1));
    }
    if (t == 1023) d_blksum[s][b] = sh[t];
}

__global__ void k_scan2() {
    __shared__ int sh[64];
    int s = blockIdx.y;
    int t = threadIdx.x;
    int v = (t < 49) ? d_blksum[s][t] : 0;
    sh[t] = v;
    __syncthreads();
    #pragma unroll
    for (int off = 1; off < 64; off <<= 1) {
        int x = (t >= off) ? sh[t - off] : 0;
        __syncthreads();
        sh[t] += x;
        __syncthreads();
    }
    if (t < 49) d_blksum[s][t] = sh[t] - v;
}

__global__ void k_scan3() {
    int s = blockIdx.y;
    int b = blockIdx.x, i = b * 1024 + threadIdx.x;
    if (i < NN) {
        int r = d_rowptr[s][i] + d_blksum[s][b];
        d_rowptr[s][i] = r;
        d_cursor[s][i] = r;
    }
    if (i == 0) d_rowptr[s][NN] = EE;
}

// fill packed edge records: {src, dinv[src]}
__global__ void k_fill(const int* __restrict__ src0, const int* __restrict__ dst0,
                       const int* __restrict__ src1, const int* __restrict__ dst1) {
    int s = blockIdx.y;
    const int* src = s ? src1 : src0;
    const int* dst = s ? dst1 : dst0;
    int e = blockIdx.x * blockDim.x + threadIdx.x;
    if (e < EE) {
        int u = src[e];
        int pos = atomicAdd(&d_cursor[s][dst[e]], 1);
        d_edge[s][pos] = make_int2(u, __float_as_int(d_dinv[s][u]));
    }
}

// ---------------- weight prep: transpose + bf16 hi/lo split ----------------
__global__ void k_prep(const float* __restrict__ Wred0, const float* __restrict__ Wred1,
                       const float* __restrict__ W0, const float* __restrict__ W1) {
    const int PER_STREAM = INDIM * HH + LLAYERS * HH * HH;
    int i = blockIdx.x * blockDim.x + threadIdx.x;
    if (i >= 2 * PER_STREAM) return;
    int s = i >= PER_STREAM;
    int j = i - s * PER_STREAM;
    float w;
    __nv_bfloat16 *ph, *pl;
    if (j < INDIM * HH) {
        int k = j >> 7, n = j & 127;
        w = (s ? Wred1 : Wred0)[k * HH + n];
        ph = &d_wredT_h[s][n * INDIM + k];
        pl = &d_wredT_l[s][n * INDIM + k];
    } else {
        int r = j - INDIM * HH;
        int l = r >> 14;
        int k = (r >> 7) & 127, n = r & 127;
        w = (s ? W1 : W0)[l * HH * HH + k * HH + n];
        ph = &d_wT_h[s][l][n * HH + k];
        pl = &d_wT_l[s][l][n * HH + k];
    }
    __nv_bfloat16 h = __float2bfloat16(w);
    *ph = h;
    *pl = __float2bfloat16(w - __bfloat162float(h));
}

// ---------------- mma.sync bf16 GEMM (3-pass compensated), batched over s ----
// Register-prefetch pipeline: A and B for tile t+1 are loaded into registers
// right after the tile-t sync, retiring under the 96-MMA compute block.
template <int KTOT, bool HOUT>
__global__ void __launch_bounds__(256) k_gemm_mma(
    const float* __restrict__ A0, const float* __restrict__ A1,
    const float* __restrict__ bias0, const float* __restrict__ bias1,
    int l, int M)
{
    constexpr int RS = 80;
    constexpr int TILE = 128 * RS;          // 10240 bytes
    constexpr int T = KTOT / 32;
    __shared__ __align__(16) char smem[4 * TILE];   // 40960 B
    const uint32_t AS_H = smem_u32(smem);
    const uint32_t AS_L = AS_H + TILE;
    const uint32_t BS_H = AS_H + 2 * TILE;
    const uint32_t BS_L = AS_H + 3 * TILE;

    int s = blockIdx.y;
    const float* A = s ? A1 : A0;
    const float* bias = s ? bias1 : bias0;
    const __nv_bfloat16* Bh = (KTOT == INDIM) ? d_wredT_h[s] : d_wT_h[s][l];
    const __nv_bfloat16* Bl = (KTOT == INDIM) ? d_wredT_l[s] : d_wT_l[s][l];

    int tid = threadIdx.x, w = tid >> 5, lane = tid & 31;
    int row0 = blockIdx.x * 128;
    int wm = (w >> 1) * 32, wn = (w & 1) * 64;

    float acc[2][8][4];
    #pragma unroll
    for (int i = 0; i < 2; i++)
        #pragma unroll
        for (int j = 0; j < 8; j++)
            #pragma unroll
            for (int q = 0; q < 4; q++) acc[i][j][q] = 0.f;

    int lrow = tid >> 1, lhalf = tid & 1;
    bool avalid = (row0 + lrow) < M;
    const float* aptr = A + (size_t)(row0 + lrow) * KTOT + lhalf * 16;
    const uint4* bhp = (const uint4*)(Bh + (size_t)lrow * KTOT + lhalf * 16);
    const uint4* blp = (const uint4*)(Bl + (size_t)lrow * KTOT + lhalf * 16);
    const int bstep = 4;                   // 32 bf16 = 64 B = 4 uint4 per k-tile
    uint32_t ld_off = (uint32_t)(lrow * RS + lhalf * 32);

    int a_r = lane & 15, a_k = (lane >> 4) * 8;
    int b_r = ((lane >> 4) << 3) + (lane & 7), b_k = ((lane >> 3) & 1) * 8;

    // ---- prologue: load tile 0 into regs ----
    float xv[16];
    uint4 bh0, bh1, bl0, bl1;
    if (avalid) {
        #pragma unroll
        for (int g = 0; g < 4; g++) {
            float4 v = *(const float4*)(aptr + g * 4);
            xv[g * 4] = v.x; xv[g * 4 + 1] = v.y; xv[g * 4 + 2] = v.z; xv[g * 4 + 3] = v.w;
        }
    } else {
        #pragma unroll
        for (int j = 0; j < 16; j++) xv[j] = 0.f;
    }
    aptr += 32;
    bh0 = bhp[0]; bh1 = bhp[1];
    bl0 = blp[0]; bl1 = blp[1];
    bhp += bstep; blp += bstep;

    #pragma unroll
    for (int t = 0; t < T; t++) {
        // stage regs -> smem
        union { uint4 q[2]; __nv_bfloat16 b[16]; } hi, lo;
        #pragma unroll
        for (int j = 0; j < 16; j++) {
            __nv_bfloat16 h = __float2bfloat16(xv[j]);
            hi.b[j] = h;
            lo.b[j] = __float2bfloat16(xv[j] - __bfloat162float(h));
        }
        STS128(AS_H + ld_off,      hi.q[0]);
        STS128(AS_H + ld_off + 16, hi.q[1]);
        STS128(AS_L + ld_off,      lo.q[0]);
        STS128(AS_L + ld_off + 16, lo.q[1]);
        STS128(BS_H + ld_off,      bh0);
        STS128(BS_H + ld_off + 16, bh1);
        STS128(BS_L + ld_off,      bl0);
        STS128(BS_L + ld_off + 16, bl1);
        __syncthreads();

        // prefetch tile t+1 into regs (issued before compute; retires underneath)
        if (t + 1 < T) {
            if (avalid) {
                #pragma unroll
                for (int g = 0; g < 4; g++) {
                    float4 v = *(const float4*)(aptr + g * 4);
                    xv[g * 4] = v.x; xv[g * 4 + 1] = v.y;
                    xv[g * 4 + 2] = v.z; xv[g * 4 + 3] = v.w;
                }
            }
            aptr += 32;
            bh0 = bhp[0]; bh1 = bhp[1];
            bl0 = blp[0]; bl1 = blp[1];
            bhp += bstep; blp += bstep;
        }

        // compute tile t
        #pragma unroll
        for (int ks = 0; ks < 2; ks++) {
            int kb = ks * 16;
            uint32_t ah[2][4], al[2][4];
            #pragma unroll
            for (int mt = 0; mt < 2; mt++) {
                uint32_t off = (uint32_t)((wm + mt * 16 + a_r) * RS + (kb + a_k) * 2);
                ldsm4(ah[mt], AS_H + off);
                ldsm4(al[mt], AS_L + off);
            }
            uint32_t bh[4][4], bl[4][4];
            #pragma unroll
            for (int nt = 0; nt < 4; nt++) {
                uint32_t off = (uint32_t)((wn + nt * 16 + b_r) * RS + (kb + b_k) * 2);
                ldsm4(bh[nt], BS_H + off);
                ldsm4(bl[nt], BS_L + off);
            }
            #pragma unroll
            for (int mt = 0; mt < 2; mt++) {
                #pragma unroll
                for (int j = 0; j < 8; j++) {
                    const uint32_t* ph = &bh[j >> 1][(j & 1) * 2];
                    const uint32_t* pl = &bl[j >> 1][(j & 1) * 2];
                    mma16816(acc[mt][j], ah[mt], ph);
                    mma16816(acc[mt][j], ah[mt], pl);
                    mma16816(acc[mt][j], al[mt], ph);
                }
            }
        }
        __syncthreads();
    }

    int qr = lane >> 2, qc = (lane & 3) * 2;
    #pragma unroll
    for (int mt = 0; mt < 2; mt++) {
        int r0g = row0 + wm + mt * 16 + qr;
        #pragma unroll
        for (int j = 0; j < 8; j++) {
            int col = wn + j * 8 + qc;
            float b0 = 0.f, b1 = 0.f;
            if (bias) { b0 = bias[col]; b1 = bias[col + 1]; }
            if (HOUT) {
                __half* Ch = d_h[s];
                if (r0g < M)
                    *(__half2*)(Ch + (size_t)r0g * HH + col) =
                        __floats2half2_rn(acc[mt][j][0] + b0, acc[mt][j][1] + b1);
                if (r0g + 8 < M)
                    *(__half2*)(Ch + (size_t)(r0g + 8) * HH + col) =
                        __floats2half2_rn(acc[mt][j][2] + b0, acc[mt][j][3] + b1);
            } else {
                float* Cf = d_x[s];
                if (r0g < M)
                    *(float2*)(Cf + (size_t)r0g * HH + col) =
                        make_float2(acc[mt][j][0] + b0, acc[mt][j][1] + b1);
                if (r0g + 8 < M)
                    *(float2*)(Cf + (size_t)(r0g + 8) * HH + col) =
                        make_float2(acc[mt][j][2] + b0, acc[mt][j][3] + b1);
            }
        }
    }
}

// ---------------- fused GCN aggregate + bias + LayerNorm + ReLU + residual ----------------
// EXACT R8 (610 us) version: warp per node; h fp16; packed (src, w) edges; 2 chains.
__global__ void __launch_bounds__(256) k_agg(
    const float* __restrict__ b0p, const float* __restrict__ b1p,
    const float* __restrict__ g0p, const float* __restrict__ g1p,
    const float* __restrict__ e0p, const float* __restrict__ e1p,
    int l)
{
    int s = blockIdx.y;
    int v = (blockIdx.x * blockDim.x + threadIdx.x) >> 5;
    int lane = threadIdx.x & 31;
    if (v >= NN) return;

    const float* bias  = (s ? b1p : b0p) + l * HH;
    const float* gamma = (s ? g1p : g0p) + l * HH;
    const float* beta  = (s ? e1p : e0p) + l * HH;
    const __half2* h2 = (const __half2*)d_h[s];   // row stride 64 half2
    const int2* edges = d_edge[s];
    float* x = d_x[s];

    float a0 = 0.f, a1 = 0.f, a2 = 0.f, a3 = 0.f;
    float c0 = 0.f, c1 = 0.f, c2 = 0.f, c3 = 0.f;
    int beg = d_rowptr[s][v], end = d_rowptr[s][v + 1];
    float dv = d_dinv[s][v];

    int i = beg;
    for (; i + 2 <= end; i += 2) {
        int2 e0 = edges[i];
        int2 e1 = edges[i + 1];
        float w0 = __int_as_float(e0.y);
        float w1 = __int_as_float(e1.y);
        const __half2* p0 = h2 + (size_t)e0.x * 64;
        const __half2* p1 = h2 + (size_t)e1.x * 64;
        float2 q00 = __half22float2(p0[lane]);
        float2 q01 = __half22float2(p0[lane + 32]);
        float2 q10 = __half22float2(p1[lane]);
        float2 q11 = __half22float2(p1[lane + 32]);
        a0 += w0 * q00.x; a1 += w0 * q00.y; a2 += w0 * q01.x; a3 += w0 * q01.y;
        c0 += w1 * q10.x; c1 += w1 * q10.y; c2 += w1 * q11.x; c3 += w1 * q11.y;
    }
    if (i < end) {
        int2 e0 = edges[i];
        float w = __int_as_float(e0.y);
        const __half2* p = h2 + (size_t)e0.x * 64;
        float2 q0 = __half22float2(p[lane]);
        float2 q1 = __half22float2(p[lane + 32]);
        a0 += w * q0.x; a1 += w * q0.y; a2 += w * q1.x; a3 += w * q1.y;
    }
    {
        const __half2* p = h2 + (size_t)v * 64;
        float2 q0 = __half22float2(p[lane]);
        float2 q1 = __half22float2(p[lane + 32]);
        a0 += c0 + dv * q0.x; a1 += c1 + dv * q0.y;
        a2 += c2 + dv * q1.x; a3 += c3 + dv * q1.y;
    }

    int ch0 = 2 * lane, ch2 = 64 + 2 * lane;
    a0 = a0 * dv + bias[ch0];
    a1 = a1 * dv + bias[ch0 + 1];
    a2 = a2 * dv + bias[ch2];
    a3 = a3 * dv + bias[ch2 + 1];

    float sum = a0 + a1 + a2 + a3;
    #pragma unroll
    for (int o = 16; o; o >>= 1) sum += __shfl_xor_sync(0xFFFFFFFFu, sum, o);
    float mu = sum * (1.f / HH);
    float v0 = a0 - mu, v1 = a1 - mu, v2 = a2 - mu, v3 = a3 - mu;
    float var = v0 * v0 + v1 * v1 + v2 * v2 + v3 * v3;
    #pragma unroll
    for (int o = 16; o; o >>= 1) var += __shfl_xor_sync(0xFFFFFFFFu, var, o);
    var *= (1.f / HH);
    float rstd = rsqrtf(var + LN_EPS);

    float2* xp = (float2*)(x + (size_t)v * HH);
    float2 r0 = xp[lane], r1 = xp[lane + 32];
    r0.x += fmaxf(v0 * rstd * gamma[ch0]     + beta[ch0],     0.f);
    r0.y += fmaxf(v1 * rstd * gamma[ch0 + 1] + beta[ch0 + 1], 0.f);
    r1.x += fmaxf(v2 * rstd * gamma[ch2]     + beta[ch2],     0.f);
    r1.y += fmaxf(v3 * rstd * gamma[ch2 + 1] + beta[ch2 + 1], 0.f);
    xp[lane] = r0;
    xp[lane + 32] = r1;
}

// ---------------- classifier ----------------
__global__ void __launch_bounds__(256) k_cls(const float* __restrict__ Wcls,
                                             const float* __restrict__ bcls,
                                             float* __restrict__ out) {
    __shared__ float WsT[CC * 2 * HH];
    __shared__ float bs[CC];
    for (int i = threadIdx.x; i < 2 * HH * CC; i += blockDim.x) {
        int k = i / CC, c = i % CC;
        WsT[c * (2 * HH) + k] = Wcls[i];
    }
    if (threadIdx.x < CC) bs[threadIdx.x] = bcls[threadIdx.x];
    __syncthreads();

    int v = (blockIdx.x * blockDim.x + threadIdx.x) >> 5;
    int lane = threadIdx.x & 31;
    if (v >= NN) return;

    float acc[CC];
    #pragma unroll
    for (int c = 0; c < CC; c++) acc[c] = 0.f;

    const float* a = d_x[0] + (size_t)v * HH;
    const float* b = d_x[1] + (size_t)v * HH;
    #pragma unroll
    for (int kk = 0; kk < 4; kk++) {
        int k = lane + 32 * kk;
        float av = a[k];
        float bv = b[k];
        #pragma unroll
        for (int c = 0; c < CC; c++) {
            acc[c] += av * WsT[c * (2 * HH) + k];
            acc[c] += bv * WsT[c * (2 * HH) + 128 + k];
        }
    }
    #pragma unroll
    for (int c = 0; c < CC; c++)
        #pragma unroll
        for (int o = 16; o; o >>= 1) acc[c] += __shfl_xor_sync(0xFFFFFFFFu, acc[c], o);

    if (lane == 0) {
        float* op = out + (size_t)v * CC;
        #pragma unroll
        for (int c = 0; c < CC; c++) op[c] = acc[c] + bs[c];
    }
}

// ---------------- driver (single default stream — graph-capture safe) ----------------
extern "C" void kernel_launch(void* const* d_in, const int* in_sizes, int n_in,
                              void* d_out, int out_size) {
    const float* x_in[2]  = { (const float*)d_in[0], (const float*)d_in[1] };
    const float* Wred[2]  = { (const float*)d_in[2], (const float*)d_in[4] };
    const float* bred[2]  = { (const float*)d_in[3], (const float*)d_in[5] };
    const float* W[2]     = { (const float*)d_in[6],  (const float*)d_in[10] };
    const float* b[2]     = { (const float*)d_in[7],  (const float*)d_in[11] };
    const float* g[2]     = { (const float*)d_in[8],  (const float*)d_in[12] };
    const float* be[2]    = { (const float*)d_in[9],  (const float*)d_in[13] };
    const float* Wcls     = (const float*)d_in[14];
    const float* bcls     = (const float*)d_in[15];
    const int*   ei[2]    = { (const int*)d_in[16], (const int*)d_in[17] };
    float* out = (float*)d_out;

    void* p0;
    cudaGetSymbolAddress(&p0, d_x);
    float* px = (float*)p0;

    const int THR = 256;
    const dim3 gN((NN + THR - 1) / THR, 2);
    const dim3 gE((EE + THR - 1) / THR, 2);
    const dim3 gW((NN * 32 + THR - 1) / THR, 2);
    const dim3 gG((NN + 127) / 128, 2);
    const dim3 gS((NN + 1023) / 1024, 2);
    const dim3 gS2(1, 2);
    const int blkWarp1 = (NN * 32 + THR - 1) / THR;

    {
        const int TOT = 2 * (INDIM * HH + LLAYERS * HH * HH);
        k_prep<<<(TOT + THR - 1) / THR, THR>>>(Wred[0], Wred[1], W[0], W[1]);
    }

    // CSR build (both streams per launch)
    k_zero<<<gN, THR>>>();
    k_hist<<<gE, THR>>>(ei[0] + EE, ei[1] + EE);
    k_scan1<<<gS, 1024>>>();
    k_scan2<<<gS2, 64>>>();
    k_scan3<<<gS, 1024>>>();
    k_fill<<<gE, THR>>>(ei[0], ei[0] + EE, ei[1], ei[1] + EE);

    // dim-reduction GEMM (both streams)
    k_gemm_mma<INDIM, false><<<gG, 256>>>(x_in[0], x_in[1], bred[0], bred[1], 0, NN);

    // 4 layers (both streams per launch)
    for (int l = 0; l < LLAYERS; l++) {
        k_gemm_mma<HH, true><<<gG, 256>>>(px, px + (size_t)NN * HH, nullptr, nullptr, l, NN);
        k_agg<<<gW, THR>>>(b[0], b[1], g[0], g[1], be[0], be[1], l);
    }

    k_cls<<<blkWarp1, THR>>>(Wcls, bcls, out);
}